// round 4
// baseline (speedup 1.0000x reference)
#include <cuda_runtime.h>
#include <cuda_bf16.h>
#include <cstdint>
#include <math.h>

// Problem dims
#define BB   256
#define TT   200
#define DD   311
#define UU   256
#define G3   768          // 3*U
#define NOUT 19
#define BT   (BB*TT)      // 51200

typedef unsigned long long u64;

// ---------------- packed f32x2 helpers (Blackwell PTX) ---------------------
__device__ __forceinline__ u64 splat2(float v) {
    u64 r; unsigned u = __float_as_uint(v);
    asm("mov.b64 %0, {%1, %1};" : "=l"(r) : "r"(u));
    return r;
}
__device__ __forceinline__ void ffma2(u64& d, u64 a, u64 b) {
    asm("fma.rn.f32x2 %0, %1, %2, %0;" : "+l"(d) : "l"(a), "l"(b));
}
__device__ __forceinline__ float lo2(u64 v) {
    return __uint_as_float((unsigned)(v & 0xffffffffull));
}
__device__ __forceinline__ float hi2(u64 v) {
    return __uint_as_float((unsigned)(v >> 32));
}

// ---------------- scratch (device globals; no cudaMalloc allowed) ----------
__device__ float g_xp[2][(size_t)BT * G3];   // input projections, per direction
__device__ float g_y [2][(size_t)BT * UU];   // hidden sequences
__device__ int   g_mask[BT];
__device__ float g_rkp[2 * 8 * 256 * 96];    // rk packed per (dir, unit-chunk)
__device__ float g_b1p[2 * 8 * 96];          // recurrent bias packed likewise

__device__ __forceinline__ float sigmoidf_(float v) {
    return 1.0f / (1.0f + expf(-v));
}

// ---------------- mask: mask[b,t] = any(x[b,t,:] != 0) ---------------------
__global__ __launch_bounds__(256) void mask_kernel(const float* __restrict__ x) {
    int warp = (blockIdx.x * blockDim.x + threadIdx.x) >> 5;
    int lane = threadIdx.x & 31;
    if (warp >= BT) return;
    const float* row = x + (size_t)warp * DD;
    int any = 0;
    for (int i = lane; i < DD; i += 32) any |= (row[i] != 0.0f);
    unsigned b = __ballot_sync(0xffffffffu, any);
    if (lane == 0) g_mask[warp] = (b != 0u);
}

// ---------------- weight pre-pack (runs once per launch, trivial) ----------
// local col c in [0,96): global col (c/32)*256 + cc*32 + (c%32)
__global__ __launch_bounds__(256) void pack_kernel(
    const float* __restrict__ rk_f, const float* __restrict__ rk_b,
    const float* __restrict__ b_f,  const float* __restrict__ b_b)
{
    int i = blockIdx.x * blockDim.x + threadIdx.x;
    const int total = 2 * 8 * 256 * 96;
    if (i < total) {
        int c   = i % 96;
        int k   = (i / 96) & 255;
        int cc  = (i / (96 * 256)) & 7;
        int dir = i / (96 * 256 * 8);
        const float* rk = dir ? rk_b : rk_f;
        g_rkp[i] = rk[(size_t)k * G3 + (c >> 5) * UU + cc * 32 + (c & 31)];
    }
    if (i < 2 * 8 * 96) {
        int c   = i % 96;
        int cc  = (i / 96) & 7;
        int dir = i / (96 * 8);
        const float* b = dir ? b_b : b_f;
        g_b1p[i] = b[G3 + (c >> 5) * UU + cc * 32 + (c & 31)];
    }
}

// ---------------- phase 1: xp[m,n] = sum_k x[m,k]*W[k,n] + b0[n] -----------
// M=51200, K=311, N=768.  128x128x8 tile, 256 thr, 8x8 per-thread (f32x2).
__global__ __launch_bounds__(256) void proj_kernel(
    const float* __restrict__ x,
    const float* __restrict__ k_f, const float* __restrict__ b_f,
    const float* __restrict__ k_b, const float* __restrict__ b_b)
{
    __shared__ float As[8 * 132];
    __shared__ float Bs[8 * 132];

    const int dir = blockIdx.z;
    const float* W    = dir ? k_b : k_f;
    const float* bias = dir ? b_b : b_f;       // row 0 = input bias
    float* xp = g_xp[dir];

    const int m0 = blockIdx.y * 128;
    const int n0 = blockIdx.x * 128;
    const int tid = threadIdx.x;
    const int tx = tid & 15;
    const int ty = tid >> 4;

    const int lxm = tid >> 1;            // 0..127
    const int lxk = (tid & 1) * 4;       // 0 or 4
    const int lbk = tid >> 5;            // 0..7
    const int lbn = (tid & 31) * 4;      // 0..124

    u64 acc2[8][4];
#pragma unroll
    for (int i = 0; i < 8; i++)
#pragma unroll
        for (int j = 0; j < 4; j++) acc2[i][j] = 0ull;

    for (int k0 = 0; k0 < DD; k0 += 8) {
#pragma unroll
        for (int j = 0; j < 4; j++) {
            int k = k0 + lxk + j;
            As[(lxk + j) * 132 + lxm] =
                (k < DD) ? __ldg(&x[(size_t)(m0 + lxm) * DD + k]) : 0.0f;
        }
        if (k0 + lbk < DD) {
            float4 v = *(const float4*)&W[(size_t)(k0 + lbk) * G3 + n0 + lbn];
            *(float4*)&Bs[lbk * 132 + lbn] = v;
        } else {
            *(float4*)&Bs[lbk * 132 + lbn] = make_float4(0.f, 0.f, 0.f, 0.f);
        }
        __syncthreads();

#pragma unroll
        for (int kk = 0; kk < 8; kk++) {
            float4 a0 = *(float4*)&As[kk * 132 + ty * 4];
            float4 a1 = *(float4*)&As[kk * 132 + 64 + ty * 4];
            const u64* bp0 = (const u64*)&Bs[kk * 132 + tx * 4];
            const u64* bp1 = (const u64*)&Bs[kk * 132 + 64 + tx * 4];
            u64 bv[4] = {bp0[0], bp0[1], bp1[0], bp1[1]};
            float av[8] = {a0.x, a0.y, a0.z, a0.w, a1.x, a1.y, a1.z, a1.w};
#pragma unroll
            for (int i = 0; i < 8; i++) {
                u64 asp = splat2(av[i]);
#pragma unroll
                for (int j = 0; j < 4; j++) ffma2(acc2[i][j], asp, bv[j]);
            }
        }
        __syncthreads();
    }

#pragma unroll
    for (int i = 0; i < 8; i++) {
        int row = m0 + ((i < 4) ? (ty * 4 + i) : (64 + ty * 4 + i - 4));
        float* o = &xp[(size_t)row * G3 + n0];
#pragma unroll
        for (int jh = 0; jh < 2; jh++) {
            int c0 = jh * 64 + tx * 4;
            float4 v;
            v.x = lo2(acc2[i][jh * 2 + 0]) + __ldg(&bias[n0 + c0 + 0]);
            v.y = hi2(acc2[i][jh * 2 + 0]) + __ldg(&bias[n0 + c0 + 1]);
            v.z = lo2(acc2[i][jh * 2 + 1]) + __ldg(&bias[n0 + c0 + 2]);
            v.w = hi2(acc2[i][jh * 2 + 1]) + __ldg(&bias[n0 + c0 + 3]);
            *(float4*)&o[c0] = v;
        }
    }
}

// ---------------- phase 2: one kernel per timestep (no cross-block sync) ---
// grid = 128: blockIdx.x = dir*64 + bg*8 + cc
//   dir: direction, bg: batch group (32 rows), cc: unit chunk (32 units).
// Each step: reload rk slice (96 KB, L2-hot) + h_prev (32 KB) into smem,
// GEMM 32x96x256 (packed f32x2), gates in registers, write y[t].
#define HS_STRIDE 260
#define SCAN_SMEM_FLOATS (256 * 96 + 32 * HS_STRIDE + 96 + 32)
#define SCAN_SMEM_BYTES  (SCAN_SMEM_FLOATS * 4)

__global__ __launch_bounds__(128) void scan_step_kernel(int s)
{
    extern __shared__ float sm[];
    float* rs   = sm;                          // [256][96] rk slice
    float* hs   = rs + 256 * 96;               // [32][260] h_prev (padded)
    float* b1s  = hs + 32 * HS_STRIDE;         // [96]
    int*   mkv  = (int*)(b1s + 96);            // [32]

    const int tid = threadIdx.x;
    const int cc  = blockIdx.x & 7;
    const int bg  = (blockIdx.x >> 3) & 7;
    const int dir = blockIdx.x >> 6;
    const int u0  = cc * 32;
    const int b0  = bg * 32;

    const int t  = dir ? (TT - 1 - s) : s;
    const int tp = dir ? (t + 1) : (t - 1);    // valid only when s > 0

    float*       y  = g_y[dir];
    const float* xp = g_xp[dir];

    // ---- fill smem ----
    {   // rk slice: contiguous float4 copy from packed layout
        const float4* src = (const float4*)(g_rkp + (size_t)(dir * 8 + cc) * 24576);
        float4* dst = (float4*)rs;
        for (int i = tid; i < 6144; i += 128) dst[i] = src[i];
    }
    if (tid < 96) b1s[tid] = g_b1p[(dir * 8 + cc) * 96 + tid];
    if (tid < 32) mkv[tid] = g_mask[(b0 + tid) * TT + t];

    if (s == 0) {
        for (int i = tid; i < 32 * HS_STRIDE; i += 128) hs[i] = 0.0f;
    } else {
        for (int i = tid; i < 2048; i += 128) {          // 32 rows x 64 float4
            int row = i >> 6, q = i & 63;
            *(float4*)&hs[row * HS_STRIDE + 4 * q] =
                *(const float4*)&y[((size_t)(b0 + row) * TT + tp) * UU + 4 * q];
        }
    }
    __syncthreads();

    // ---- GEMM: thread (rt, ct) -> rows rt+{0,8,16,24}, units u0+2ct+{0,1},
    //      all three gates (cols 2ct, 32+2ct, 64+2ct of the packed slice) ----
    const int rt = tid & 7;
    const int ct = tid >> 3;          // 0..15

    u64 acc[4][3];
#pragma unroll
    for (int i = 0; i < 4; i++)
#pragma unroll
        for (int j = 0; j < 3; j++) acc[i][j] = 0ull;

#pragma unroll 8
    for (int k = 0; k < 256; k++) {
        const float* rk = &rs[k * 96];
        u64 wz = *(const u64*)&rk[2 * ct];
        u64 wr = *(const u64*)&rk[32 + 2 * ct];
        u64 wh = *(const u64*)&rk[64 + 2 * ct];
        u64 hp0 = splat2(hs[(rt     ) * HS_STRIDE + k]);
        u64 hp1 = splat2(hs[(rt +  8) * HS_STRIDE + k]);
        u64 hp2 = splat2(hs[(rt + 16) * HS_STRIDE + k]);
        u64 hp3 = splat2(hs[(rt + 24) * HS_STRIDE + k]);
        ffma2(acc[0][0], hp0, wz); ffma2(acc[0][1], hp0, wr); ffma2(acc[0][2], hp0, wh);
        ffma2(acc[1][0], hp1, wz); ffma2(acc[1][1], hp1, wr); ffma2(acc[1][2], hp1, wh);
        ffma2(acc[2][0], hp2, wz); ffma2(acc[2][1], hp2, wr); ffma2(acc[2][2], hp2, wh);
        ffma2(acc[3][0], hp3, wz); ffma2(acc[3][1], hp3, wr); ffma2(acc[3][2], hp3, wh);
    }

    // ---- gates (registers only) ----
    const float bz0 = b1s[2 * ct],      bz1 = b1s[2 * ct + 1];
    const float br0 = b1s[32 + 2 * ct], br1 = b1s[32 + 2 * ct + 1];
    const float bh0 = b1s[64 + 2 * ct], bh1 = b1s[64 + 2 * ct + 1];

#pragma unroll
    for (int i = 0; i < 4; i++) {
        int row = rt + 8 * i;
        int gb  = b0 + row;
        size_t base = ((size_t)gb * TT + t) * G3 + u0 + 2 * ct;
        float2 xz = *(const float2*)&xp[base];
        float2 xr = *(const float2*)&xp[base + UU];
        float2 xh = *(const float2*)&xp[base + 2 * UU];
        float2 hp = *(const float2*)&hs[row * HS_STRIDE + u0 + 2 * ct];

        float rzA = lo2(acc[i][0]) + bz0, rzB = hi2(acc[i][0]) + bz1;
        float rrA = lo2(acc[i][1]) + br0, rrB = hi2(acc[i][1]) + br1;
        float rhA = lo2(acc[i][2]) + bh0, rhB = hi2(acc[i][2]) + bh1;

        float zA = sigmoidf_(xz.x + rzA), zB = sigmoidf_(xz.y + rzB);
        float rA = sigmoidf_(xr.x + rrA), rB = sigmoidf_(xr.y + rrB);
        float hhA = tanhf(xh.x + rA * rhA), hhB = tanhf(xh.y + rB * rhB);
        float hnA = zA * hp.x + (1.0f - zA) * hhA;
        float hnB = zB * hp.y + (1.0f - zB) * hhB;
        if (!mkv[row]) { hnA = hp.x; hnB = hp.y; }

        *(float2*)&y[((size_t)gb * TT + t) * UU + u0 + 2 * ct] =
            make_float2(hnA, hnB);
    }
}

// ---------------- phase 3: dense + softmax ---------------------------------
__global__ __launch_bounds__(256) void dense_kernel(
    const float* __restrict__ w_d, const float* __restrict__ b_d,
    float* __restrict__ out)
{
    __shared__ float ws[2 * UU * NOUT];   // 512*19
    __shared__ float bs[NOUT];
    for (int i = threadIdx.x; i < 2 * UU * NOUT; i += 256) ws[i] = w_d[i];
    if (threadIdx.x < NOUT) bs[threadIdx.x] = b_d[threadIdx.x];
    __syncthreads();

    int warp = threadIdx.x >> 5, lane = threadIdx.x & 31;
    int row = blockIdx.x * 8 + warp;               // 6400 * 8 = 51200 exact
    const float* hf = g_y[0] + (size_t)row * UU;
    const float* hb = g_y[1] + (size_t)row * UU;

    float acc[NOUT];
#pragma unroll
    for (int o = 0; o < NOUT; o++) acc[o] = 0.0f;

    for (int j = lane; j < UU; j += 32) {
        float a = hf[j];
        const float* w = &ws[j * NOUT];
#pragma unroll
        for (int o = 0; o < NOUT; o++) acc[o] += a * w[o];
        float b = hb[j];
        const float* w2 = &ws[(UU + j) * NOUT];
#pragma unroll
        for (int o = 0; o < NOUT; o++) acc[o] += b * w2[o];
    }
#pragma unroll
    for (int off = 16; off > 0; off >>= 1)
#pragma unroll
        for (int o = 0; o < NOUT; o++)
            acc[o] += __shfl_xor_sync(0xffffffffu, acc[o], off);

#pragma unroll
    for (int o = 0; o < NOUT; o++) acc[o] += bs[o];
    float m = acc[0];
#pragma unroll
    for (int o = 1; o < NOUT; o++) m = fmaxf(m, acc[o]);
    float sum = 0.0f;
#pragma unroll
    for (int o = 0; o < NOUT; o++) { acc[o] = expf(acc[o] - m); sum += acc[o]; }
    float inv = 1.0f / sum;

    if (lane < NOUT) {
        float v = 0.0f;
#pragma unroll
        for (int o = 0; o < NOUT; o++) if (lane == o) v = acc[o];
        out[(size_t)row * NOUT + lane] = v * inv;
    }
}

// ---------------- launch ----------------------------------------------------
extern "C" void kernel_launch(void* const* d_in, const int* in_sizes, int n_in,
                              void* d_out, int out_size)
{
    const float* x    = (const float*)d_in[0];
    const float* k_f  = (const float*)d_in[1];
    const float* rk_f = (const float*)d_in[2];
    const float* b_f  = (const float*)d_in[3];
    const float* k_b  = (const float*)d_in[4];
    const float* rk_b = (const float*)d_in[5];
    const float* b_b  = (const float*)d_in[6];
    const float* w_d  = (const float*)d_in[7];
    const float* b_d  = (const float*)d_in[8];
    float* out = (float*)d_out;

    // mask + weight pack + input projections
    mask_kernel<<<BT / 8, 256>>>(x);
    pack_kernel<<<(2 * 8 * 256 * 96 + 255) / 256, 256>>>(rk_f, rk_b, b_f, b_b);
    dim3 pg(G3 / 128, BT / 128, 2);
    proj_kernel<<<pg, 256>>>(x, k_f, b_f, k_b, b_b);

    // recurrent scan: one plain launch per timestep (no inter-block sync)
    static int smem_set = 0;
    if (!smem_set) {
        cudaFuncSetAttribute(scan_step_kernel,
                             cudaFuncAttributeMaxDynamicSharedMemorySize,
                             SCAN_SMEM_BYTES);
        smem_set = 1;
    }
    for (int s = 0; s < TT; s++)
        scan_step_kernel<<<128, 128, SCAN_SMEM_BYTES>>>(s);

    // dense + softmax
    dense_kernel<<<BT / 8, 256>>>(w_d, b_d, out);
}

// round 6
// speedup vs baseline: 1.3691x; 1.3691x over previous
#include <cuda_runtime.h>
#include <cuda_bf16.h>
#include <cstdint>
#include <math.h>

// Problem dims
#define BB   256
#define TT   200
#define DD   311
#define UU   256
#define G3   768          // 3*U
#define NOUT 19
#define BT   (BB*TT)      // 51200

typedef unsigned long long u64;

// ---------------- packed f32x2 helpers (Blackwell PTX) ---------------------
__device__ __forceinline__ u64 splat2(float v) {
    u64 r; unsigned u = __float_as_uint(v);
    asm("mov.b64 %0, {%1, %1};" : "=l"(r) : "r"(u));
    return r;
}
__device__ __forceinline__ void ffma2(u64& d, u64 a, u64 b) {
    asm("fma.rn.f32x2 %0, %1, %2, %0;" : "+l"(d) : "l"(a), "l"(b));
}
__device__ __forceinline__ float lo2(u64 v) {
    return __uint_as_float((unsigned)(v & 0xffffffffull));
}
__device__ __forceinline__ float hi2(u64 v) {
    return __uint_as_float((unsigned)(v >> 32));
}

// ---------------- scratch (device globals; no cudaMalloc allowed) ----------
__device__ float g_xp[2][(size_t)BT * G3];   // input projections, per direction
__device__ float g_y [2][(size_t)BT * UU];   // hidden sequences
__device__ int   g_mask[BT];
__device__ float g_rkp[2 * 8 * 256 * 96];    // rk packed per (dir, unit-chunk)
__device__ float g_b1p[2 * 8 * 96];          // recurrent bias packed likewise

__device__ __forceinline__ float sigmoidf_(float v) {
    return 1.0f / (1.0f + expf(-v));
}

// ---------------- mask: mask[b,t] = any(x[b,t,:] != 0) ---------------------
__global__ __launch_bounds__(256) void mask_kernel(const float* __restrict__ x) {
    int warp = (blockIdx.x * blockDim.x + threadIdx.x) >> 5;
    int lane = threadIdx.x & 31;
    if (warp >= BT) return;
    const float* row = x + (size_t)warp * DD;
    int any = 0;
    for (int i = lane; i < DD; i += 32) any |= (row[i] != 0.0f);
    unsigned b = __ballot_sync(0xffffffffu, any);
    if (lane == 0) g_mask[warp] = (b != 0u);
}

// ---------------- weight pre-pack (runs once per launch, trivial) ----------
// local col c in [0,96): global col (c/32)*256 + cc*32 + (c%32)
__global__ __launch_bounds__(256) void pack_kernel(
    const float* __restrict__ rk_f, const float* __restrict__ rk_b,
    const float* __restrict__ b_f,  const float* __restrict__ b_b)
{
    int i = blockIdx.x * blockDim.x + threadIdx.x;
    const int total = 2 * 8 * 256 * 96;
    if (i < total) {
        int c   = i % 96;
        int k   = (i / 96) & 255;
        int cc  = (i / (96 * 256)) & 7;
        int dir = i / (96 * 256 * 8);
        const float* rk = dir ? rk_b : rk_f;
        g_rkp[i] = rk[(size_t)k * G3 + (c >> 5) * UU + cc * 32 + (c & 31)];
    }
    if (i < 2 * 8 * 96) {
        int c   = i % 96;
        int cc  = (i / 96) & 7;
        int dir = i / (96 * 8);
        const float* b = dir ? b_b : b_f;
        g_b1p[i] = b[G3 + (c >> 5) * UU + cc * 32 + (c & 31)];
    }
}

// ---------------- phase 1: xp[m,n] = sum_k x[m,k]*W[k,n] + b0[n] -----------
// M=51200, K=311, N=768.  128x128x8 tile, 256 thr, 8x8 per-thread (f32x2).
__global__ __launch_bounds__(256) void proj_kernel(
    const float* __restrict__ x,
    const float* __restrict__ k_f, const float* __restrict__ b_f,
    const float* __restrict__ k_b, const float* __restrict__ b_b)
{
    __shared__ float As[8 * 132];
    __shared__ float Bs[8 * 132];

    const int dir = blockIdx.z;
    const float* W    = dir ? k_b : k_f;
    const float* bias = dir ? b_b : b_f;       // row 0 = input bias
    float* xp = g_xp[dir];

    const int m0 = blockIdx.y * 128;
    const int n0 = blockIdx.x * 128;
    const int tid = threadIdx.x;
    const int tx = tid & 15;
    const int ty = tid >> 4;

    const int lxm = tid >> 1;            // 0..127
    const int lxk = (tid & 1) * 4;       // 0 or 4
    const int lbk = tid >> 5;            // 0..7
    const int lbn = (tid & 31) * 4;      // 0..124

    u64 acc2[8][4];
#pragma unroll
    for (int i = 0; i < 8; i++)
#pragma unroll
        for (int j = 0; j < 4; j++) acc2[i][j] = 0ull;

    for (int k0 = 0; k0 < DD; k0 += 8) {
#pragma unroll
        for (int j = 0; j < 4; j++) {
            int k = k0 + lxk + j;
            As[(lxk + j) * 132 + lxm] =
                (k < DD) ? __ldg(&x[(size_t)(m0 + lxm) * DD + k]) : 0.0f;
        }
        if (k0 + lbk < DD) {
            float4 v = *(const float4*)&W[(size_t)(k0 + lbk) * G3 + n0 + lbn];
            *(float4*)&Bs[lbk * 132 + lbn] = v;
        } else {
            *(float4*)&Bs[lbk * 132 + lbn] = make_float4(0.f, 0.f, 0.f, 0.f);
        }
        __syncthreads();

#pragma unroll
        for (int kk = 0; kk < 8; kk++) {
            float4 a0 = *(float4*)&As[kk * 132 + ty * 4];
            float4 a1 = *(float4*)&As[kk * 132 + 64 + ty * 4];
            const u64* bp0 = (const u64*)&Bs[kk * 132 + tx * 4];
            const u64* bp1 = (const u64*)&Bs[kk * 132 + 64 + tx * 4];
            u64 bv[4] = {bp0[0], bp0[1], bp1[0], bp1[1]};
            float av[8] = {a0.x, a0.y, a0.z, a0.w, a1.x, a1.y, a1.z, a1.w};
#pragma unroll
            for (int i = 0; i < 8; i++) {
                u64 asp = splat2(av[i]);
#pragma unroll
                for (int j = 0; j < 4; j++) ffma2(acc2[i][j], asp, bv[j]);
            }
        }
        __syncthreads();
    }

#pragma unroll
    for (int i = 0; i < 8; i++) {
        int row = m0 + ((i < 4) ? (ty * 4 + i) : (64 + ty * 4 + i - 4));
        float* o = &xp[(size_t)row * G3 + n0];
#pragma unroll
        for (int jh = 0; jh < 2; jh++) {
            int c0 = jh * 64 + tx * 4;
            float4 v;
            v.x = lo2(acc2[i][jh * 2 + 0]) + __ldg(&bias[n0 + c0 + 0]);
            v.y = hi2(acc2[i][jh * 2 + 0]) + __ldg(&bias[n0 + c0 + 1]);
            v.z = lo2(acc2[i][jh * 2 + 1]) + __ldg(&bias[n0 + c0 + 2]);
            v.w = hi2(acc2[i][jh * 2 + 1]) + __ldg(&bias[n0 + c0 + 3]);
            *(float4*)&o[c0] = v;
        }
    }
}

// ---------------- phase 2: one kernel per timestep (no cross-block sync) ---
// grid = 128: blockIdx.x = dir*64 + bg*8 + cc
//   dir: direction, bg: batch group (32 rows), cc: unit chunk (32 units).
// 256 threads (8 warps -> 2 warps/SMSP for latency hiding).
// Thread (rt, ct): rows {rt, rt+16}, units u0+2ct+{0,1}, all 3 gates.
// w-pair LDS are warp-broadcast (all rt-lanes share ct).
#define HS_STRIDE 260
#define SCAN_SMEM_FLOATS (256 * 96 + 32 * HS_STRIDE + 96 + 32)
#define SCAN_SMEM_BYTES  (SCAN_SMEM_FLOATS * 4)

__global__ __launch_bounds__(256) void scan_step_kernel(int s)
{
    extern __shared__ float sm[];
    float* rs   = sm;                          // [256][96] rk slice
    float* hs   = rs + 256 * 96;               // [32][260] h_prev (padded)
    float* b1s  = hs + 32 * HS_STRIDE;         // [96]
    int*   mkv  = (int*)(b1s + 96);            // [32]

    const int tid = threadIdx.x;
    const int cc  = blockIdx.x & 7;
    const int bg  = (blockIdx.x >> 3) & 7;
    const int dir = blockIdx.x >> 6;
    const int u0  = cc * 32;
    const int b0  = bg * 32;

    const int t  = dir ? (TT - 1 - s) : s;
    const int tp = dir ? (t + 1) : (t - 1);    // valid only when s > 0

    float*       y  = g_y[dir];
    const float* xp = g_xp[dir];

    // ---- fill smem ----
    {   // rk slice: contiguous float4 copy from packed layout (L2-hot)
        const float4* src = (const float4*)(g_rkp + (size_t)(dir * 8 + cc) * 24576);
        float4* dst = (float4*)rs;
#pragma unroll
        for (int i = 0; i < 24; i++) dst[tid + 256 * i] = src[tid + 256 * i];
    }
    if (tid < 96) b1s[tid] = g_b1p[(dir * 8 + cc) * 96 + tid];
    if (tid >= 128 && tid < 160) mkv[tid - 128] = g_mask[(b0 + tid - 128) * TT + t];

    if (s == 0) {
        for (int i = tid; i < 32 * HS_STRIDE; i += 256) hs[i] = 0.0f;
    } else {
#pragma unroll
        for (int i = 0; i < 8; i++) {            // 32 rows x 64 float4
            int idx = tid + 256 * i;
            int row = idx >> 6, q = idx & 63;
            *(float4*)&hs[row * HS_STRIDE + 4 * q] =
                *(const float4*)&y[((size_t)(b0 + row) * TT + tp) * UU + 4 * q];
        }
    }
    __syncthreads();

    // ---- GEMM 32x96x256: thread (rt, ct) -> rows {rt, rt+16},
    //      packed col-pairs {2ct,2ct+1} of each gate (offsets 0/32/64) ----
    const int rt = tid & 15;          // 0..15
    const int ct = tid >> 4;          // 0..15

    u64 acc[2][3];
#pragma unroll
    for (int i = 0; i < 2; i++)
#pragma unroll
        for (int j = 0; j < 3; j++) acc[i][j] = 0ull;

    const float* hrow0 = &hs[rt * HS_STRIDE];
    const float* hrow1 = &hs[(rt + 16) * HS_STRIDE];

#pragma unroll 8
    for (int k = 0; k < 256; k++) {
        const float* rk = &rs[k * 96];
        u64 wz = *(const u64*)&rk[2 * ct];        // warp-broadcast
        u64 wr = *(const u64*)&rk[32 + 2 * ct];
        u64 wh = *(const u64*)&rk[64 + 2 * ct];
        u64 hp0 = splat2(hrow0[k]);
        u64 hp1 = splat2(hrow1[k]);
        ffma2(acc[0][0], hp0, wz); ffma2(acc[0][1], hp0, wr); ffma2(acc[0][2], hp0, wh);
        ffma2(acc[1][0], hp1, wz); ffma2(acc[1][1], hp1, wr); ffma2(acc[1][2], hp1, wh);
    }

    // ---- gates (registers only) ----
    const float bz0 = b1s[2 * ct],      bz1 = b1s[2 * ct + 1];
    const float br0 = b1s[32 + 2 * ct], br1 = b1s[32 + 2 * ct + 1];
    const float bh0 = b1s[64 + 2 * ct], bh1 = b1s[64 + 2 * ct + 1];

#pragma unroll
    for (int i = 0; i < 2; i++) {
        int row = rt + 16 * i;
        int gb  = b0 + row;
        size_t base = ((size_t)gb * TT + t) * G3 + u0 + 2 * ct;
        float2 xz = *(const float2*)&xp[base];
        float2 xr = *(const float2*)&xp[base + UU];
        float2 xh = *(const float2*)&xp[base + 2 * UU];
        float2 hp = *(const float2*)&hs[row * HS_STRIDE + u0 + 2 * ct];

        float rzA = lo2(acc[i][0]) + bz0, rzB = hi2(acc[i][0]) + bz1;
        float rrA = lo2(acc[i][1]) + br0, rrB = hi2(acc[i][1]) + br1;
        float rhA = lo2(acc[i][2]) + bh0, rhB = hi2(acc[i][2]) + bh1;

        float zA = sigmoidf_(xz.x + rzA), zB = sigmoidf_(xz.y + rzB);
        float rA = sigmoidf_(xr.x + rrA), rB = sigmoidf_(xr.y + rrB);
        float hhA = tanhf(xh.x + rA * rhA), hhB = tanhf(xh.y + rB * rhB);
        float hnA = zA * hp.x + (1.0f - zA) * hhA;
        float hnB = zB * hp.y + (1.0f - zB) * hhB;
        if (!mkv[row]) { hnA = hp.x; hnB = hp.y; }

        *(float2*)&y[((size_t)gb * TT + t) * UU + u0 + 2 * ct] =
            make_float2(hnA, hnB);
    }
}

// ---------------- phase 3: dense + softmax ---------------------------------
__global__ __launch_bounds__(256) void dense_kernel(
    const float* __restrict__ w_d, const float* __restrict__ b_d,
    float* __restrict__ out)
{
    __shared__ float ws[2 * UU * NOUT];   // 512*19
    __shared__ float bs[NOUT];
    for (int i = threadIdx.x; i < 2 * UU * NOUT; i += 256) ws[i] = w_d[i];
    if (threadIdx.x < NOUT) bs[threadIdx.x] = b_d[threadIdx.x];
    __syncthreads();

    int warp = threadIdx.x >> 5, lane = threadIdx.x & 31;
    int row = blockIdx.x * 8 + warp;               // 6400 * 8 = 51200 exact
    const float* hf = g_y[0] + (size_t)row * UU;
    const float* hb = g_y[1] + (size_t)row * UU;

    float acc[NOUT];
#pragma unroll
    for (int o = 0; o < NOUT; o++) acc[o] = 0.0f;

    for (int j = lane; j < UU; j += 32) {
        float a = hf[j];
        const float* w = &ws[j * NOUT];
#pragma unroll
        for (int o = 0; o < NOUT; o++) acc[o] += a * w[o];
        float b = hb[j];
        const float* w2 = &ws[(UU + j) * NOUT];
#pragma unroll
        for (int o = 0; o < NOUT; o++) acc[o] += b * w2[o];
    }
#pragma unroll
    for (int off = 16; off > 0; off >>= 1)
#pragma unroll
        for (int o = 0; o < NOUT; o++)
            acc[o] += __shfl_xor_sync(0xffffffffu, acc[o], off);

#pragma unroll
    for (int o = 0; o < NOUT; o++) acc[o] += bs[o];
    float m = acc[0];
#pragma unroll
    for (int o = 1; o < NOUT; o++) m = fmaxf(m, acc[o]);
    float sum = 0.0f;
#pragma unroll
    for (int o = 0; o < NOUT; o++) { acc[o] = expf(acc[o] - m); sum += acc[o]; }
    float inv = 1.0f / sum;

    if (lane < NOUT) {
        float v = 0.0f;
#pragma unroll
        for (int o = 0; o < NOUT; o++) if (lane == o) v = acc[o];
        out[(size_t)row * NOUT + lane] = v * inv;
    }
}

// ---------------- launch ----------------------------------------------------
extern "C" void kernel_launch(void* const* d_in, const int* in_sizes, int n_in,
                              void* d_out, int out_size)
{
    const float* x    = (const float*)d_in[0];
    const float* k_f  = (const float*)d_in[1];
    const float* rk_f = (const float*)d_in[2];
    const float* b_f  = (const float*)d_in[3];
    const float* k_b  = (const float*)d_in[4];
    const float* rk_b = (const float*)d_in[5];
    const float* b_b  = (const float*)d_in[6];
    const float* w_d  = (const float*)d_in[7];
    const float* b_d  = (const float*)d_in[8];
    float* out = (float*)d_out;

    // mask + weight pack + input projections
    mask_kernel<<<BT / 8, 256>>>(x);
    pack_kernel<<<(2 * 8 * 256 * 96 + 255) / 256, 256>>>(rk_f, rk_b, b_f, b_b);
    dim3 pg(G3 / 128, BT / 128, 2);
    proj_kernel<<<pg, 256>>>(x, k_f, b_f, k_b, b_b);

    // recurrent scan: one plain launch per timestep (no inter-block sync)
    cudaFuncSetAttribute(scan_step_kernel,
                         cudaFuncAttributeMaxDynamicSharedMemorySize,
                         SCAN_SMEM_BYTES);
    for (int s = 0; s < TT; s++)
        scan_step_kernel<<<128, 256, SCAN_SMEM_BYTES>>>(s);

    // dense + softmax
    dense_kernel<<<BT / 8, 256>>>(w_d, b_d, out);
}